// round 13
// baseline (speedup 1.0000x reference)
#include <cuda_runtime.h>
#include <cuda_bf16.h>
#include <math.h>
#include <stdint.h>

#define EPS 1e-8f

#define C_CLUST 1024
#define S_SAMP  16
#define D_DIM   512
#define NROWS   (C_CLUST * S_SAMP)   // 16384

#define NCTA 148                // all co-resident: software grid barrier is safe
#define NT 256                  // N-tile -> 4 tiles
#define KC 64
#define NTILES 4
#define NC 32
#define NTHREADS 256
#define MAXMT 7                 // max clusters (m16 units) per CTA
#define A_CH_B   (MAXMT * 16 * 128)       // 14336 per K-chunk
#define A_BYTES  (8 * A_CH_B)             // 114688
#define B_CHUNK_B (NT * KC * 2)           // 32768 (also the x staging slab size)
#define NBUF 3
#define SMALL_B  4096
#define DYN_SMEM (SMALL_B + A_BYTES + NBUF * B_CHUNK_B + 256)  // 217344 <= 232448

// ---------------------------------------------------------------------------
// Globals: only B-side products cross CTAs now. A stays in smem.
// ---------------------------------------------------------------------------
__device__ __nv_bfloat16 g_Bbf[C_CLUST * D_DIM];  // 1 MB (mean centroids [k][d])
__device__ float g_invnm[C_CLUST];
__device__ unsigned int g_ready = 0;              // monotonic ticket (never reset)

// ---------------------------------------------------------------------------
// helpers
// ---------------------------------------------------------------------------
__device__ __forceinline__ uint32_t smem_u32(const void* p) {
    uint32_t a;
    asm("{ .reg .u64 t; cvta.to.shared.u64 t, %1; cvt.u32.u64 %0, t; }" : "=r"(a) : "l"(p));
    return a;
}
__device__ __forceinline__ void cp_async16(uint32_t dst, const void* src) {
    asm volatile("cp.async.cg.shared.global [%0], [%1], 16;\n" :: "r"(dst), "l"(src) : "memory");
}
__device__ __forceinline__ void cp_commit() {
    asm volatile("cp.async.commit_group;\n" ::: "memory");
}
template <int N> __device__ __forceinline__ void cp_wait() {
    asm volatile("cp.async.wait_group %0;\n" :: "n"(N) : "memory");
}
__device__ __forceinline__ void ldsm4(uint32_t* r, uint32_t addr) {
    asm volatile("ldmatrix.sync.aligned.m8n8.x4.shared.b16 {%0,%1,%2,%3}, [%4];"
                 : "=r"(r[0]), "=r"(r[1]), "=r"(r[2]), "=r"(r[3]) : "r"(addr));
}
__device__ __forceinline__ void mma16816(float* c, const uint32_t* a, uint32_t b0, uint32_t b1) {
    asm volatile("mma.sync.aligned.m16n8k16.row.col.f32.bf16.bf16.f32 "
                 "{%0,%1,%2,%3}, {%4,%5,%6,%7}, {%8,%9}, {%0,%1,%2,%3};"
                 : "+f"(c[0]), "+f"(c[1]), "+f"(c[2]), "+f"(c[3])
                 : "r"(a[0]), "r"(a[1]), "r"(a[2]), "r"(a[3]), "r"(b0), "r"(b1));
}
__device__ __forceinline__ uint32_t sw_addr(uint32_t base, int row, int kseg) {
    return base + (uint32_t)(row << 7) + (uint32_t)(((kseg ^ (row & 7)) & 7) << 4);
}

// ---------------------------------------------------------------------------
// Fused kernel: phase1 stats+convert (own clusters) | grid barrier | phase2 GEMM
// 148 CTAs x 256 threads. CTA c owns clusters [s16, s16+nmt).
// ---------------------------------------------------------------------------
__global__ void __launch_bounds__(NTHREADS, 1) k_fused(const float* __restrict__ x,
                                                       const float* __restrict__ wptr,
                                                       float* __restrict__ out)
{
    extern __shared__ char rawsm[];
    char* smbase = (char*)(((uintptr_t)rawsm + 127u) & ~(uintptr_t)127u);

    float* s_invnx = (float*)smbase;            // 112
    float* s_sp    = s_invnx + 112;             // 112
    float* s_ssum  = s_sp + 112;                // 512
    float* s_wred  = s_ssum + 512;              // 8
    float* s_sumsq = s_wred + 8;                // 1
    char*  smA_p   = smbase + SMALL_B;
    const uint32_t smA = smem_u32(smA_p);
    const uint32_t smB = smA + A_BYTES;
    char*  smB_p   = smA_p + A_BYTES;
    // final-reduction arrays alias the B ring (dead after the main loop):
    float* s_red     = (float*)(smA_p + A_BYTES);   // 8*112
    float* s_rowloss = s_red + 8 * 112;             // 112
    float* s_part    = s_rowloss + 112;             // 8

    const int tid  = threadIdx.x;
    const int lane = tid & 31;
    const int wn   = tid >> 5;          // warp id
    const int lq   = lane >> 3, l7 = lane & 7;

    const int c    = blockIdx.x;
    const int s16  = (c < 136) ? c * 7 : 952 + (c - 136) * 6;
    const int nmt  = (c < 136) ? 7 : 6;
    const int nr   = nmt * 16;

    if (c == 0 && tid == 0) out[0] = 0.f;   // release-ordered by the ticket fence

    // ================= PHASE 1: stats + bf16 conversion ====================
    // Staging: cluster u's x slab (16x512 fp32 = 32KB) in B slot (u&1).
    auto stage_x = [&](int u) {
        const uint32_t dst = smB + (uint32_t)(u & 1) * B_CHUNK_B;
        const float* src = x + (size_t)(s16 + u) * S_SAMP * D_DIM;
        #pragma unroll
        for (int it = 0; it < 8; it++) {
            const int i = tid + it * 256;     // 0..2047 x 16B
            cp_async16(dst + (uint32_t)i * 16u, (const char*)src + (size_t)i * 16u);
        }
        cp_commit();
    };

    stage_x(0);
    if (nmt > 1) stage_x(1);

    #pragma unroll 1
    for (int u = 0; u < nmt; u++) {
        const int j = s16 + u;
        if (u + 1 < nmt) cp_wait<1>(); else cp_wait<0>();
        __syncthreads();                       // staging u visible; prior reads done
        if (u + 2 < nmt) stage_x(u + 2);

        const float* stg = (const float*)(smB_p + (u & 1) * B_CHUNK_B);  // [16][512]

        // bf16 conversion -> swizzled A slab (rows u*16..u*16+15)
        #pragma unroll
        for (int it = 0; it < 4; it++) {
            const int i  = tid + it * 256;     // 0..1023 segments
            const int r  = i >> 6;             // row in cluster
            const int s7 = i & 63;             // 8-elem segment
            const float4 v0 = *(const float4*)(stg + r * D_DIM + s7 * 8);
            const float4 v1 = *(const float4*)(stg + r * D_DIM + s7 * 8 + 4);
            unsigned short h[8];
            h[0] = __bfloat16_as_ushort(__float2bfloat16(v0.x));
            h[1] = __bfloat16_as_ushort(__float2bfloat16(v0.y));
            h[2] = __bfloat16_as_ushort(__float2bfloat16(v0.z));
            h[3] = __bfloat16_as_ushort(__float2bfloat16(v0.w));
            h[4] = __bfloat16_as_ushort(__float2bfloat16(v1.x));
            h[5] = __bfloat16_as_ushort(__float2bfloat16(v1.y));
            h[6] = __bfloat16_as_ushort(__float2bfloat16(v1.z));
            h[7] = __bfloat16_as_ushort(__float2bfloat16(v1.w));
            uint4 pk;
            pk.x = ((uint32_t)h[1] << 16) | h[0];
            pk.y = ((uint32_t)h[3] << 16) | h[2];
            pk.z = ((uint32_t)h[5] << 16) | h[4];
            pk.w = ((uint32_t)h[7] << 16) | h[6];
            const int R  = u * 16 + r;
            const int kc = s7 >> 3, sg = s7 & 7;
            *(uint4*)(smA_p + kc * A_CH_B + (R << 7) + (((sg ^ (R & 7)) & 7) << 4)) = pk;
        }

        // column sums over the 16 rows; write Bbf (bf16 mean) to global
        const int d0 = tid, d1 = tid + 256;
        float s0 = 0.f, s1 = 0.f;
        #pragma unroll
        for (int i = 0; i < S_SAMP; i++) {
            s0 += stg[i * D_DIM + d0];
            s1 += stg[i * D_DIM + d1];
        }
        s_ssum[d0] = s0;
        s_ssum[d1] = s1;
        g_Bbf[(size_t)j * D_DIM + d0] = __float2bfloat16(s0 * (1.f / 16.f));
        g_Bbf[(size_t)j * D_DIM + d1] = __float2bfloat16(s1 * (1.f / 16.f));

        float p = s0 * s0 + s1 * s1;
        #pragma unroll
        for (int off = 16; off; off >>= 1) p += __shfl_down_sync(0xffffffffu, p, off);
        if (lane == 0) s_wred[wn] = p;
        __syncthreads();
        if (tid == 0) {
            float t = 0.f;
            #pragma unroll
            for (int wi = 0; wi < 8; wi++) t += s_wred[wi];
            s_sumsq[0] = t;
            g_invnm[j] = 16.f / sqrtf(t);
        }
        __syncthreads();
        const float sumsq = s_sumsq[0];

        // per-row norms / sim_pos -> smem only (A side never leaves the CTA)
        #pragma unroll
        for (int rr = 0; rr < 2; rr++) {
            const int i = wn + rr * 8;
            float nx2 = 0.f, dt = 0.f;
            #pragma unroll
            for (int cc = 0; cc < 16; cc++) {
                const int d = lane + cc * 32;
                const float a = stg[i * D_DIM + d];
                nx2 += a * a;
                dt  += a * s_ssum[d];
            }
            #pragma unroll
            for (int off = 16; off; off >>= 1) {
                nx2 += __shfl_down_sync(0xffffffffu, nx2, off);
                dt  += __shfl_down_sync(0xffffffffu, dt,  off);
            }
            if (lane == 0) {
                const float loo_dot = (dt - nx2) * (1.f / 15.f);
                const float nloo2   = fmaxf((sumsq - 2.f * dt + nx2) * (1.f / 225.f), 0.f);
                const float nx      = sqrtf(nx2);
                s_invnx[u * 16 + i] = 1.f / nx;
                s_sp[u * 16 + i]    = loo_dot / fmaxf(nx * sqrtf(nloo2), EPS);
            }
        }
    }

    // ================= GRID BARRIER (replay-safe monotonic ticket) =========
    __syncthreads();
    if (tid == 0) {
        __threadfence();
        const unsigned int my = atomicAdd(&g_ready, 1u) + 1u;
        const unsigned int target = ((my + NCTA - 1u) / NCTA) * NCTA;
        unsigned int v;
        do {
            asm volatile("ld.acquire.gpu.global.u32 %0, [%1];"
                         : "=r"(v) : "l"(&g_ready));
        } while (v < target);
    }
    __syncthreads();   // publishes all CTAs' Bbf/invnm (+ out=0) to the block

    // ================= PHASE 2: GEMM + fused logsumexp =====================
    const float wp = log1pf(expf(wptr[0]));

    // warp-private B chunk loader: rows [wn*32, +32) of slot gg%NBUF
    auto load_B = [&](int gg) {
        const uint32_t slot = smB + (uint32_t)(gg % NBUF) * B_CHUNK_B;
        const __nv_bfloat16* bsrc =
            g_Bbf + (size_t)((gg >> 3) * NT + wn * 32) * D_DIM + (gg & 7) * KC;
        #pragma unroll
        for (int it = 0; it < 8; it++) {
            const int i = lane + it * 32;        // 0..255
            const int r = i >> 3, s = i & 7;     // r 0..31
            const int row = wn * 32 + r;
            cp_async16(slot + (uint32_t)(row << 7) +
                           (uint32_t)(((s ^ (row & 7)) & 7) << 4),
                       bsrc + (size_t)r * D_DIM + s * 8);
        }
        cp_commit();
    };

    load_B(0);
    load_B(1);
    cp_wait<1>();
    __syncwarp();

    float acc[MAXMT][4][4];
    #pragma unroll
    for (int mt = 0; mt < MAXMT; mt++)
        #pragma unroll
        for (int p = 0; p < 4; p++)
            #pragma unroll
            for (int e = 0; e < 4; e++) acc[mt][p][e] = 0.f;

    float es[MAXMT][2];
    #pragma unroll
    for (int mt = 0; mt < MAXMT; mt++) { es[mt][0] = 0.f; es[mt][1] = 0.f; }

    auto mma_chunk = [&](int kcA, int slot) {
        const uint32_t Ac = smA + (uint32_t)kcA * A_CH_B;
        const uint32_t Bs = smB + (uint32_t)slot * B_CHUNK_B;
        #pragma unroll
        for (int k16 = 0; k16 < 4; k16++) {
            uint32_t a[MAXMT][4];
            #pragma unroll
            for (int mt = 0; mt < MAXMT; mt++)
                if (mt < nmt)
                    ldsm4(a[mt], sw_addr(Ac, mt * 16 + (lq & 1) * 8 + l7,
                                         k16 * 2 + (lq >> 1)));
            uint32_t b[2][4];
            #pragma unroll
            for (int p2 = 0; p2 < 2; p2++)
                ldsm4(b[p2], sw_addr(Bs, wn * 32 + p2 * 16 + (lq >> 1) * 8 + l7,
                                     k16 * 2 + (lq & 1)));
            #pragma unroll
            for (int p2 = 0; p2 < 2; p2++)
                #pragma unroll
                for (int mt = 0; mt < MAXMT; mt++)
                    if (mt < nmt) {
                        mma16816(acc[mt][p2 * 2],     a[mt], b[p2][0], b[p2][1]);
                        mma16816(acc[mt][p2 * 2 + 1], a[mt], b[p2][2], b[p2][3]);
                    }
        }
    };

    auto epi_tile = [&](int t) {
        #pragma unroll
        for (int p = 0; p < 4; p++) {
            const int c0  = t * NT + wn * 32 + p * 8 + (lane & 3) * 2;
            const float nm0 = __ldg(&g_invnm[c0]);
            const float nm1 = __ldg(&g_invnm[c0 + 1]);
            #pragma unroll
            for (int mt = 0; mt < MAXMT; mt++) {
                if (mt >= nmt) break;
                const int jr = s16 + mt;
                #pragma unroll
                for (int h = 0; h < 2; h++) {
                    const int rl = mt * 16 + h * 8 + (lane >> 2);
                    const float inx = s_invnx[rl];
                    float v0 = acc[mt][p][h * 2 + 0] * inx * nm0;
                    float v1 = acc[mt][p][h * 2 + 1] * inx * nm1;
                    if (c0     == jr) v0 = s_sp[rl];
                    if (c0 + 1 == jr) v1 = s_sp[rl];
                    es[mt][h] += __expf(wp * v0) + __expf(wp * v1);
                    acc[mt][p][h * 2 + 0] = 0.f;
                    acc[mt][p][h * 2 + 1] = 0.f;
                }
            }
        }
    };

    #pragma unroll 1
    for (int t = 0; t < NTILES; t++) {
        #pragma unroll
        for (int kc = 0; kc < 8; kc++) {
            const int g = t * 8 + kc;
            if (g > 0) {
                if (g < NC - 1) cp_wait<1>(); else cp_wait<0>();
                __syncwarp();
            }
            if (g + 2 < NC) load_B(g + 2);
            mma_chunk(kc, g % NBUF);
        }
        epi_tile(t);
    }

    __syncthreads();   // all warps done; safe to alias B ring with s_red

    #pragma unroll
    for (int mt = 0; mt < MAXMT; mt++) {
        if (mt >= nmt) break;
        #pragma unroll
        for (int h = 0; h < 2; h++) {
            float v = es[mt][h];
            v += __shfl_xor_sync(0xffffffffu, v, 1);
            v += __shfl_xor_sync(0xffffffffu, v, 2);
            if ((lane & 3) == 0)
                s_red[wn * 112 + mt * 16 + h * 8 + (lane >> 2)] = v;
        }
    }
    __syncthreads();
    if (tid < nr) {
        float tot = 0.f;
        #pragma unroll
        for (int w = 0; w < 8; w++) tot += s_red[w * 112 + tid];
        s_rowloss[tid] = logf(tot) - wp * s_sp[tid];
    }
    __syncthreads();
    {
        float v = (tid < nr) ? s_rowloss[tid] : 0.f;
        #pragma unroll
        for (int off = 16; off; off >>= 1) v += __shfl_down_sync(0xffffffffu, v, off);
        if (lane == 0) s_part[wn] = v;
    }
    __syncthreads();
    if (tid == 0) {
        float t = 0.f;
        #pragma unroll
        for (int i = 0; i < 8; i++) t += s_part[i];
        atomicAdd(out, t * (1.f / (float)NROWS));
    }
}

extern "C" void kernel_launch(void* const* d_in, const int* in_sizes, int n_in,
                              void* d_out, int out_size)
{
    const float* x = (const float*)d_in[0];
    const float* w = (const float*)d_in[1];
    // b cancels: lse(wp*sim + b) - (wp*sim_pos + b) is b-independent.
    float* out = (float*)d_out;

    cudaFuncSetAttribute(k_fused, cudaFuncAttributeMaxDynamicSharedMemorySize, DYN_SMEM);

    k_fused<<<NCTA, NTHREADS, DYN_SMEM>>>(x, w, out);
}